// round 2
// baseline (speedup 1.0000x reference)
#include <cuda_runtime.h>
#include <cuda_bf16.h>

#define N_NODES 100000
#define N_EDGES 1600000
#define IN_F    64
#define N_CLS   64

// Scratch: g = feat @ W^T  (25.6 MB), row_start (CSR offsets from sorted COO rows)
__device__ float g_buf[(size_t)N_NODES * N_CLS];
__device__ int   g_row_start[N_NODES + 1];

// ---------------------------------------------------------------------------
// Kernel 1: row_start[r] = lower_bound(edge_row, r)   (edge_row is sorted)
// ---------------------------------------------------------------------------
__global__ void rowptr_kernel(const int* __restrict__ edge_row, int* __restrict__ row_start) {
    int r = blockIdx.x * blockDim.x + threadIdx.x;
    if (r > N_NODES) return;
    int lo = 0, hi = N_EDGES;
    while (lo < hi) {
        int mid = (lo + hi) >> 1;
        if (edge_row[mid] < r) lo = mid + 1; else hi = mid;
    }
    row_start[r] = lo;
}

// ---------------------------------------------------------------------------
// Kernel 2: g = feat @ W^T    feat [N,64], W [64,64] (row-major [c][f])
// Tile: 128 rows per block, 256 threads, each thread computes 8 rows x 4 cols.
// ---------------------------------------------------------------------------
#define TILE_ROWS 128
__global__ __launch_bounds__(256) void gemm_kernel(const float* __restrict__ feat,
                                                   const float* __restrict__ W,
                                                   float* __restrict__ g) {
    __shared__ float sA[TILE_ROWS * 64];   // feat tile [row][k]
    __shared__ float sWt[64 * 64];         // W transposed: [k][c]

    int tid  = threadIdx.x;
    int row0 = blockIdx.x * TILE_ROWS;
    int maxrow = N_NODES - row0;           // valid rows in this tile

    // Load W transposed into smem: sWt[f*64 + c] = W[c*64 + f]
    for (int idx = tid; idx < 64 * 64; idx += 256) {
        int c = idx >> 6, f = idx & 63;
        sWt[f * 64 + c] = W[idx];
    }
    // Load feat tile (float4 vectorized), zero-pad past end
    {
        const float4* fp = (const float4*)(feat + (size_t)row0 * 64);
        float4* sp = (float4*)sA;
        for (int idx = tid; idx < TILE_ROWS * 16; idx += 256) {
            int r = idx >> 4;
            sp[idx] = (r < maxrow) ? fp[idx] : make_float4(0.f, 0.f, 0.f, 0.f);
        }
    }
    __syncthreads();

    int tx = tid & 15;   // col group: cols [tx*4, tx*4+4)
    int ty = tid >> 4;   // row group: rows [ty*8, ty*8+8)

    float acc[8][4];
    #pragma unroll
    for (int i = 0; i < 8; ++i)
        #pragma unroll
        for (int j = 0; j < 4; ++j) acc[i][j] = 0.f;

    #pragma unroll 4
    for (int k = 0; k < 64; ++k) {
        float4 w = ((const float4*)(sWt + k * 64))[tx];
        float a[8];
        #pragma unroll
        for (int i = 0; i < 8; ++i) a[i] = sA[(ty * 8 + i) * 64 + k];
        #pragma unroll
        for (int i = 0; i < 8; ++i) {
            acc[i][0] = fmaf(a[i], w.x, acc[i][0]);
            acc[i][1] = fmaf(a[i], w.y, acc[i][1]);
            acc[i][2] = fmaf(a[i], w.z, acc[i][2]);
            acc[i][3] = fmaf(a[i], w.w, acc[i][3]);
        }
    }

    #pragma unroll
    for (int i = 0; i < 8; ++i) {
        int r = ty * 8 + i;
        if (r < maxrow) {
            float4 v = make_float4(acc[i][0], acc[i][1], acc[i][2], acc[i][3]);
            ((float4*)(g + (size_t)(row0 + r) * 64))[tx] = v;
        }
    }
}

// ---------------------------------------------------------------------------
// Kernel 3: out[r,:] = sum_e val[e] * g[col[e],:]  + b     (one warp per node)
// Each lane owns a float2 (2 of 64 features). No atomics (rows sorted -> CSR).
// ---------------------------------------------------------------------------
__global__ __launch_bounds__(256) void spmm_kernel(const int* __restrict__ row_start,
                                                   const int* __restrict__ edge_col,
                                                   const float* __restrict__ edge_val,
                                                   const float* __restrict__ g,
                                                   const float* __restrict__ b,
                                                   float* __restrict__ out) {
    int warp = (blockIdx.x * blockDim.x + threadIdx.x) >> 5;
    int lane = threadIdx.x & 31;
    if (warp >= N_NODES) return;

    int s = row_start[warp];
    int e = row_start[warp + 1];

    const float2* gp = (const float2*)g;
    float2 acc = make_float2(0.f, 0.f);

    int i = s;
    // 4x unroll for memory-level parallelism (avg degree = 16)
    for (; i + 3 < e; i += 4) {
        int   c0 = __ldg(&edge_col[i]);
        int   c1 = __ldg(&edge_col[i + 1]);
        int   c2 = __ldg(&edge_col[i + 2]);
        int   c3 = __ldg(&edge_col[i + 3]);
        float v0 = __ldg(&edge_val[i]);
        float v1 = __ldg(&edge_val[i + 1]);
        float v2 = __ldg(&edge_val[i + 2]);
        float v3 = __ldg(&edge_val[i + 3]);
        float2 a0 = gp[(size_t)c0 * 32 + lane];
        float2 a1 = gp[(size_t)c1 * 32 + lane];
        float2 a2 = gp[(size_t)c2 * 32 + lane];
        float2 a3 = gp[(size_t)c3 * 32 + lane];
        acc.x = fmaf(v0, a0.x, acc.x);  acc.y = fmaf(v0, a0.y, acc.y);
        acc.x = fmaf(v1, a1.x, acc.x);  acc.y = fmaf(v1, a1.y, acc.y);
        acc.x = fmaf(v2, a2.x, acc.x);  acc.y = fmaf(v2, a2.y, acc.y);
        acc.x = fmaf(v3, a3.x, acc.x);  acc.y = fmaf(v3, a3.y, acc.y);
    }
    for (; i < e; ++i) {
        int   c = __ldg(&edge_col[i]);
        float v = __ldg(&edge_val[i]);
        float2 a = gp[(size_t)c * 32 + lane];
        acc.x = fmaf(v, a.x, acc.x);
        acc.y = fmaf(v, a.y, acc.y);
    }

    float2 bv = ((const float2*)b)[lane];
    acc.x += bv.x;
    acc.y += bv.y;
    ((float2*)out)[(size_t)warp * 32 + lane] = acc;
}

// ---------------------------------------------------------------------------
extern "C" void kernel_launch(void* const* d_in, const int* in_sizes, int n_in,
                              void* d_out, int out_size) {
    const float* feat     = (const float*)d_in[0];
    const int*   edge_row = (const int*)  d_in[1];
    const int*   edge_col = (const int*)  d_in[2];
    const float* edge_val = (const float*)d_in[3];
    const float* W        = (const float*)d_in[4];
    const float* b        = (const float*)d_in[5];
    float*       out      = (float*)d_out;

    float* g;
    int*   row_start;
    cudaGetSymbolAddress((void**)&g, g_buf);
    cudaGetSymbolAddress((void**)&row_start, g_row_start);

    // 1) CSR offsets from sorted COO rows
    rowptr_kernel<<<(N_NODES + 1 + 255) / 256, 256>>>(edge_row, row_start);

    // 2) g = feat @ W^T
    gemm_kernel<<<(N_NODES + TILE_ROWS - 1) / TILE_ROWS, 256>>>(feat, W, g);

    // 3) out = A @ g + b   (one warp per node)
    int total_threads = N_NODES * 32;
    spmm_kernel<<<(total_threads + 255) / 256, 256>>>(row_start, edge_col, edge_val,
                                                      g, b, out);
}

// round 3
// speedup vs baseline: 1.0673x; 1.0673x over previous
#include <cuda_runtime.h>
#include <cuda_fp16.h>
#include <cuda_bf16.h>
#include <cstdint>

#define N_NODES 100000
#define N_EDGES 1600000
#define IN_F    64
#define N_CLS   64

// Scratch: g = feat @ W^T in fp16 (12.8 MB -> stays L2-resident), CSR offsets
__device__ __half g_buf[(size_t)N_NODES * N_CLS];
__device__ int    g_row_start[N_NODES + 1];

// ---------------------------------------------------------------------------
// f32x2 packed-FMA helpers (fma.rn.f32x2 — not emitted by ptxas from C++)
// ---------------------------------------------------------------------------
__device__ __forceinline__ unsigned long long fma2(unsigned long long a,
                                                   unsigned long long b,
                                                   unsigned long long c) {
    unsigned long long d;
    asm("fma.rn.f32x2 %0, %1, %2, %3;" : "=l"(d) : "l"(a), "l"(b), "l"(c));
    return d;
}
__device__ __forceinline__ void unpack2(unsigned long long v, float& lo, float& hi) {
    asm("mov.b64 {%0, %1}, %2;" : "=f"(lo), "=f"(hi) : "l"(v));
}

// ---------------------------------------------------------------------------
// Kernel 1: row_start from sorted COO rows via transition scan.
// row_start[q] = lower_bound(edge_row, q). Thread e writes rows in
// (edge_row[e-1], edge_row[e]] as e. Thread 0 / last handle the ends.
// ---------------------------------------------------------------------------
__global__ void rowptr_scan_kernel(const int* __restrict__ edge_row,
                                   int* __restrict__ row_start) {
    int e = blockIdx.x * blockDim.x + threadIdx.x;
    if (e >= N_EDGES) return;
    int r = edge_row[e];
    if (e == 0) {
        for (int q = 0; q <= r; ++q) row_start[q] = 0;
    } else {
        int rp = edge_row[e - 1];
        for (int q = rp + 1; q <= r; ++q) row_start[q] = e;
    }
    if (e == N_EDGES - 1) {
        for (int q = r + 1; q <= N_NODES; ++q) row_start[q] = N_EDGES;
    }
}

// ---------------------------------------------------------------------------
// Kernel 2: g = half( feat @ W^T )
// 128 rows/block, 256 threads, 8 rows x 4 cols per thread, fma.rn.f32x2.
// A-tile stored DUPLICATED ((a,a) float2) so the packed broadcast operand is
// one LDS.64; W pair (c,c+1) is contiguous -> one LDS.64.
// ---------------------------------------------------------------------------
#define TILE_ROWS 128
__global__ __launch_bounds__(256) void gemm_kernel(const float* __restrict__ feat,
                                                   const float* __restrict__ W,
                                                   __half* __restrict__ g) {
    __shared__ float2 sAd[TILE_ROWS * 64];  // (a,a) duplicated: 64 KB
    __shared__ float  sWt[64 * 64];         // W^T: [k][c], 16 KB

    int tid  = threadIdx.x;
    int row0 = blockIdx.x * TILE_ROWS;
    int maxrow = N_NODES - row0;

    // W^T into smem
    for (int idx = tid; idx < 64 * 64; idx += 256) {
        int c = idx >> 6, f = idx & 63;
        sWt[f * 64 + c] = W[idx];
    }
    // feat tile, duplicated per element
    {
        const float4* fp = (const float4*)(feat + (size_t)row0 * 64);
        for (int idx = tid; idx < TILE_ROWS * 16; idx += 256) {
            int r = idx >> 4, p = idx & 15;
            float4 v = (r < maxrow) ? fp[idx] : make_float4(0.f, 0.f, 0.f, 0.f);
            float2* dst = sAd + r * 64 + p * 4;
            dst[0] = make_float2(v.x, v.x);
            dst[1] = make_float2(v.y, v.y);
            dst[2] = make_float2(v.z, v.z);
            dst[3] = make_float2(v.w, v.w);
        }
    }
    __syncthreads();

    int tx = tid & 15;   // cols [tx*4, tx*4+4)
    int ty = tid >> 4;   // rows [ty*8, ty*8+8)

    unsigned long long acc[8][2];
    #pragma unroll
    for (int i = 0; i < 8; ++i) { acc[i][0] = 0ull; acc[i][1] = 0ull; }

    const unsigned long long* sAul = (const unsigned long long*)sAd;
    const unsigned long long* sWul = (const unsigned long long*)sWt;

    #pragma unroll 4
    for (int k = 0; k < 64; ++k) {
        unsigned long long w01 = sWul[k * 32 + tx * 2];      // (w[c], w[c+1])
        unsigned long long w23 = sWul[k * 32 + tx * 2 + 1];  // (w[c+2], w[c+3])
        #pragma unroll
        for (int i = 0; i < 8; ++i) {
            unsigned long long aa = sAul[(ty * 8 + i) * 64 + k];  // (a, a)
            acc[i][0] = fma2(aa, w01, acc[i][0]);
            acc[i][1] = fma2(aa, w23, acc[i][1]);
        }
    }

    #pragma unroll
    for (int i = 0; i < 8; ++i) {
        int r = ty * 8 + i;
        if (r < maxrow) {
            float f0, f1, f2, f3;
            unpack2(acc[i][0], f0, f1);
            unpack2(acc[i][1], f2, f3);
            __half2 h0 = __floats2half2_rn(f0, f1);
            __half2 h1 = __floats2half2_rn(f2, f3);
            uint2 pv = make_uint2(*(const unsigned*)&h0, *(const unsigned*)&h1);
            *(uint2*)(g + (size_t)(row0 + r) * 64 + tx * 4) = pv;
        }
    }
}

// ---------------------------------------------------------------------------
// Kernel 3: out[r,:] = sum_e val[e] * g_half[col[e],:] + b   (one warp/node)
// Each lane owns 2 features as one half2 -> warp gathers one 128B line/edge.
// ---------------------------------------------------------------------------
__global__ __launch_bounds__(256) void spmm_kernel(const int* __restrict__ row_start,
                                                   const int* __restrict__ edge_col,
                                                   const float* __restrict__ edge_val,
                                                   const __half* __restrict__ g,
                                                   const float* __restrict__ b,
                                                   float* __restrict__ out) {
    int warp = (blockIdx.x * blockDim.x + threadIdx.x) >> 5;
    int lane = threadIdx.x & 31;
    if (warp >= N_NODES) return;

    int s = row_start[warp];
    int e = row_start[warp + 1];

    const __half2* gp = (const __half2*)g;   // row stride = 32 half2
    float accx = 0.f, accy = 0.f;

    int i = s;
    for (; i + 3 < e; i += 4) {
        int   c0 = __ldg(&edge_col[i]);
        int   c1 = __ldg(&edge_col[i + 1]);
        int   c2 = __ldg(&edge_col[i + 2]);
        int   c3 = __ldg(&edge_col[i + 3]);
        float v0 = __ldg(&edge_val[i]);
        float v1 = __ldg(&edge_val[i + 1]);
        float v2 = __ldg(&edge_val[i + 2]);
        float v3 = __ldg(&edge_val[i + 3]);
        float2 a0 = __half22float2(gp[(size_t)c0 * 32 + lane]);
        float2 a1 = __half22float2(gp[(size_t)c1 * 32 + lane]);
        float2 a2 = __half22float2(gp[(size_t)c2 * 32 + lane]);
        float2 a3 = __half22float2(gp[(size_t)c3 * 32 + lane]);
        accx = fmaf(v0, a0.x, accx);  accy = fmaf(v0, a0.y, accy);
        accx = fmaf(v1, a1.x, accx);  accy = fmaf(v1, a1.y, accy);
        accx = fmaf(v2, a2.x, accx);  accy = fmaf(v2, a2.y, accy);
        accx = fmaf(v3, a3.x, accx);  accy = fmaf(v3, a3.y, accy);
    }
    for (; i < e; ++i) {
        int   c = __ldg(&edge_col[i]);
        float v = __ldg(&edge_val[i]);
        float2 a = __half22float2(gp[(size_t)c * 32 + lane]);
        accx = fmaf(v, a.x, accx);
        accy = fmaf(v, a.y, accy);
    }

    float2 bv = ((const float2*)b)[lane];
    float2 r = make_float2(accx + bv.x, accy + bv.y);
    ((float2*)out)[(size_t)warp * 32 + lane] = r;
}

// ---------------------------------------------------------------------------
extern "C" void kernel_launch(void* const* d_in, const int* in_sizes, int n_in,
                              void* d_out, int out_size) {
    const float* feat     = (const float*)d_in[0];
    const int*   edge_row = (const int*)  d_in[1];
    const int*   edge_col = (const int*)  d_in[2];
    const float* edge_val = (const float*)d_in[3];
    const float* W        = (const float*)d_in[4];
    const float* b        = (const float*)d_in[5];
    float*       out      = (float*)d_out;

    __half* g;
    int*    row_start;
    cudaGetSymbolAddress((void**)&g, g_buf);
    cudaGetSymbolAddress((void**)&row_start, g_row_start);

    // 1) CSR offsets via transition scan over sorted rows
    rowptr_scan_kernel<<<(N_EDGES + 255) / 256, 256>>>(edge_row, row_start);

    // 2) g = half(feat @ W^T), f32x2 packed FMA
    gemm_kernel<<<(N_NODES + TILE_ROWS - 1) / TILE_ROWS, 256>>>(feat, W, g);

    // 3) out = A @ g + b
    int total_threads = N_NODES * 32;
    spmm_kernel<<<(total_threads + 255) / 256, 256>>>(row_start, edge_col, edge_val,
                                                      g, b, out);
}

// round 4
// speedup vs baseline: 1.5465x; 1.4490x over previous
#include <cuda_runtime.h>
#include <cuda_fp16.h>
#include <cuda_bf16.h>
#include <cstdint>

#define N_NODES 100000
#define N_EDGES 1600000
#define IN_F    64
#define N_CLS   64

// Scratch: g = feat @ W^T in fp16 (12.8 MB -> L2-resident), CSR offsets
__device__ __half g_buf[(size_t)N_NODES * N_CLS];
__device__ int    g_row_start[N_NODES + 1];

// ---------------------------------------------------------------------------
// Kernel 1: row_start via vectorized transition scan (4 edges per thread).
// row_start[q] = lower_bound(edge_row, q); edge_row sorted. N_EDGES % 4 == 0.
// ---------------------------------------------------------------------------
__global__ __launch_bounds__(256) void rowptr_kernel(const int* __restrict__ edge_row,
                                                     int* __restrict__ row_start) {
    int t = blockIdx.x * blockDim.x + threadIdx.x;
    if (t >= N_EDGES / 4) return;
    int4 r4 = ((const int4*)edge_row)[t];
    int e0 = t * 4;
    int prev = (t == 0) ? -1 : __ldg(&edge_row[e0 - 1]);

    for (int q = prev + 1; q <= r4.x; ++q) row_start[q] = e0;
    for (int q = r4.x + 1; q <= r4.y; ++q) row_start[q] = e0 + 1;
    for (int q = r4.y + 1; q <= r4.z; ++q) row_start[q] = e0 + 2;
    for (int q = r4.z + 1; q <= r4.w; ++q) row_start[q] = e0 + 3;

    if (e0 + 4 == N_EDGES) {
        for (int q = r4.w + 1; q <= N_NODES; ++q) row_start[q] = N_EDGES;
    }
}

// ---------------------------------------------------------------------------
// tf32 mma helpers
// ---------------------------------------------------------------------------
__device__ __forceinline__ unsigned f2tf32(float x) {
    unsigned u;
    asm("cvt.rna.tf32.f32 %0, %1;" : "=r"(u) : "f"(x));
    return u;
}
__device__ __forceinline__ void mma_tf32(float& c0, float& c1, float& c2, float& c3,
                                         unsigned a0, unsigned a1, unsigned a2, unsigned a3,
                                         unsigned b0, unsigned b1) {
    asm("mma.sync.aligned.m16n8k8.row.col.f32.tf32.tf32.f32 "
        "{%0,%1,%2,%3}, {%4,%5,%6,%7}, {%8,%9}, {%0,%1,%2,%3};"
        : "+f"(c0), "+f"(c1), "+f"(c2), "+f"(c3)
        : "r"(a0), "r"(a1), "r"(a2), "r"(a3), "r"(b0), "r"(b1));
}

// ---------------------------------------------------------------------------
// Kernel 2: g = half( feat @ W^T )  via tf32 tensor-core mma (m16n8k8).
// Block: 256 threads (8 warps), tile 64 rows x 64 cols.
// Warp grid 4x2: warp_m in [0,4) owns 16 rows, warp_n in [0,2) owns 32 cols.
// smem padded stride 68 floats -> conflict-free fragment loads.
// ---------------------------------------------------------------------------
#define GEMM_ROWS 64
#define SM_PAD 68
__global__ __launch_bounds__(256) void gemm_tc_kernel(const float* __restrict__ feat,
                                                      const float* __restrict__ W,
                                                      __half* __restrict__ g) {
    __shared__ float sA[GEMM_ROWS * SM_PAD];  // feat tile [r][k], 17.4 KB
    __shared__ float sB[64 * SM_PAD];         // W [n][k],        17.4 KB

    int tid  = threadIdx.x;
    int lane = tid & 31;
    int warp = tid >> 5;
    int row0 = blockIdx.x * GEMM_ROWS;
    int maxrow = N_NODES - row0;

    // Load W [64][64] row-major -> sB[n*68+k]  (float4 per thread-iter)
    for (int idx = tid; idx < 64 * 16; idx += 256) {
        int n = idx >> 4, q = idx & 15;
        float4 v = ((const float4*)W)[idx];
        float* dst = &sB[n * SM_PAD + q * 4];
        dst[0] = v.x; dst[1] = v.y; dst[2] = v.z; dst[3] = v.w;
    }
    // Load feat tile [64][64] -> sA[r*68+k]
    for (int idx = tid; idx < GEMM_ROWS * 16; idx += 256) {
        int r = idx >> 4, q = idx & 15;
        float4 v = (r < maxrow) ? __ldcs(&((const float4*)(feat + (size_t)row0 * 64))[idx])
                                : make_float4(0.f, 0.f, 0.f, 0.f);
        float* dst = &sA[r * SM_PAD + q * 4];
        dst[0] = v.x; dst[1] = v.y; dst[2] = v.z; dst[3] = v.w;
    }
    __syncthreads();

    int g4 = lane >> 2;      // group id (0..7)
    int t4 = lane & 3;       // thread in group (0..3)
    int warp_m = warp >> 1;  // 0..3 -> rows warp_m*16
    int warp_n = warp & 1;   // 0..1 -> ntiles warp_n*4 + nt

    float acc[4][4];
    #pragma unroll
    for (int i = 0; i < 4; ++i)
        #pragma unroll
        for (int j = 0; j < 4; ++j) acc[i][j] = 0.f;

    int ra = warp_m * 16 + g4;

    #pragma unroll
    for (int ks = 0; ks < 8; ++ks) {
        int k0 = ks * 8;
        // A fragment (m16k8, row-major)
        unsigned a0 = f2tf32(sA[ra * SM_PAD + k0 + t4]);
        unsigned a1 = f2tf32(sA[(ra + 8) * SM_PAD + k0 + t4]);
        unsigned a2 = f2tf32(sA[ra * SM_PAD + k0 + t4 + 4]);
        unsigned a3 = f2tf32(sA[(ra + 8) * SM_PAD + k0 + t4 + 4]);
        #pragma unroll
        for (int nt = 0; nt < 4; ++nt) {
            int n = (warp_n * 4 + nt) * 8 + g4;
            // B fragment (k8n8, col-major): b0 = B[k][n] = W[n][k]
            unsigned b0 = f2tf32(sB[n * SM_PAD + k0 + t4]);
            unsigned b1 = f2tf32(sB[n * SM_PAD + k0 + t4 + 4]);
            mma_tf32(acc[nt][0], acc[nt][1], acc[nt][2], acc[nt][3],
                     a0, a1, a2, a3, b0, b1);
        }
    }

    // Epilogue: c0,c1 -> (row ra, cols col,col+1); c2,c3 -> row ra+8
    #pragma unroll
    for (int nt = 0; nt < 4; ++nt) {
        int col = (warp_n * 4 + nt) * 8 + 2 * t4;
        if (ra < maxrow) {
            __half2 h = __floats2half2_rn(acc[nt][0], acc[nt][1]);
            *(__half2*)(g + (size_t)(row0 + ra) * 64 + col) = h;
        }
        if (ra + 8 < maxrow) {
            __half2 h = __floats2half2_rn(acc[nt][2], acc[nt][3]);
            *(__half2*)(g + (size_t)(row0 + ra + 8) * 64 + col) = h;
        }
    }
}

// ---------------------------------------------------------------------------
// Kernel 3: out[r,:] = sum_e val[e] * g_half[col[e],:] + b   (one warp/node)
// Each lane owns 2 features (half2) -> one 128B line gathered per edge.
// Edge streams use .cs (evict-first) to protect g's L2 residency; out uses .cs.
// MLP raised to 8 via unroll.
// ---------------------------------------------------------------------------
__global__ __launch_bounds__(256) void spmm_kernel(const int* __restrict__ row_start,
                                                   const int* __restrict__ edge_col,
                                                   const float* __restrict__ edge_val,
                                                   const __half* __restrict__ g,
                                                   const float* __restrict__ b,
                                                   float* __restrict__ out) {
    int warp = (blockIdx.x * blockDim.x + threadIdx.x) >> 5;
    int lane = threadIdx.x & 31;
    if (warp >= N_NODES) return;

    int s = row_start[warp];
    int e = row_start[warp + 1];

    const __half2* gp = (const __half2*)g;   // row stride = 32 half2
    float accx = 0.f, accy = 0.f;

    int i = s;
    for (; i + 7 < e; i += 8) {
        int c[8]; float v[8];
        #pragma unroll
        for (int j = 0; j < 8; ++j) {
            c[j] = __ldcs(&edge_col[i + j]);
            v[j] = __ldcs(&edge_val[i + j]);
        }
        float2 a[8];
        #pragma unroll
        for (int j = 0; j < 8; ++j)
            a[j] = __half22float2(gp[(size_t)c[j] * 32 + lane]);
        #pragma unroll
        for (int j = 0; j < 8; ++j) {
            accx = fmaf(v[j], a[j].x, accx);
            accy = fmaf(v[j], a[j].y, accy);
        }
    }
    for (; i + 3 < e; i += 4) {
        int c[4]; float v[4];
        #pragma unroll
        for (int j = 0; j < 4; ++j) {
            c[j] = __ldcs(&edge_col[i + j]);
            v[j] = __ldcs(&edge_val[i + j]);
        }
        float2 a[4];
        #pragma unroll
        for (int j = 0; j < 4; ++j)
            a[j] = __half22float2(gp[(size_t)c[j] * 32 + lane]);
        #pragma unroll
        for (int j = 0; j < 4; ++j) {
            accx = fmaf(v[j], a[j].x, accx);
            accy = fmaf(v[j], a[j].y, accy);
        }
    }
    for (; i < e; ++i) {
        int   c = __ldcs(&edge_col[i]);
        float v = __ldcs(&edge_val[i]);
        float2 a = __half22float2(gp[(size_t)c * 32 + lane]);
        accx = fmaf(v, a.x, accx);
        accy = fmaf(v, a.y, accy);
    }

    float2 bv = ((const float2*)b)[lane];
    float2 r = make_float2(accx + bv.x, accy + bv.y);
    __stcs(&((float2*)out)[(size_t)warp * 32 + lane], r);
}

// ---------------------------------------------------------------------------
extern "C" void kernel_launch(void* const* d_in, const int* in_sizes, int n_in,
                              void* d_out, int out_size) {
    const float* feat     = (const float*)d_in[0];
    const int*   edge_row = (const int*)  d_in[1];
    const int*   edge_col = (const int*)  d_in[2];
    const float* edge_val = (const float*)d_in[3];
    const float* W        = (const float*)d_in[4];
    const float* b        = (const float*)d_in[5];
    float*       out      = (float*)d_out;

    __half* g;
    int*    row_start;
    cudaGetSymbolAddress((void**)&g, g_buf);
    cudaGetSymbolAddress((void**)&row_start, g_row_start);

    // 1) CSR offsets via vectorized transition scan
    rowptr_kernel<<<(N_EDGES / 4 + 255) / 256, 256>>>(edge_row, row_start);

    // 2) g = half(feat @ W^T), tf32 tensor cores
    gemm_tc_kernel<<<(N_NODES + GEMM_ROWS - 1) / GEMM_ROWS, 256>>>(feat, W, g);

    // 3) out = A @ g + b   (one warp per node)
    int total_threads = N_NODES * 32;
    spmm_kernel<<<(total_threads + 255) / 256, 256>>>(row_start, edge_col, edge_val,
                                                      g, b, out);
}

// round 5
// speedup vs baseline: 1.6320x; 1.0553x over previous
#include <cuda_runtime.h>
#include <cuda_fp16.h>
#include <cuda_bf16.h>
#include <cstdint>

#define N_NODES 100000
#define N_EDGES 1600000
#define IN_F    64
#define N_CLS   64

// Scratch: g = feat @ W^T in fp16 (12.8 MB -> L2-resident), CSR offsets
__device__ __half g_buf[(size_t)N_NODES * N_CLS];
__device__ int    g_row_start[N_NODES + 1];

#define NB_ROW  ((N_EDGES / 4 + 255) / 256)   /* 1563 rowptr blocks  */
#define NB_GEMM ((N_NODES + 63) / 64)         /* 1563 gemm blocks    */

// ---------------------------------------------------------------------------
// tf32 mma helpers
// ---------------------------------------------------------------------------
__device__ __forceinline__ unsigned f2tf32(float x) {
    unsigned u;
    asm("cvt.rna.tf32.f32 %0, %1;" : "=r"(u) : "f"(x));
    return u;
}
__device__ __forceinline__ void mma_tf32(float& c0, float& c1, float& c2, float& c3,
                                         unsigned a0, unsigned a1, unsigned a2, unsigned a3,
                                         unsigned b0, unsigned b1) {
    asm("mma.sync.aligned.m16n8k8.row.col.f32.tf32.tf32.f32 "
        "{%0,%1,%2,%3}, {%4,%5,%6,%7}, {%8,%9}, {%0,%1,%2,%3};"
        : "+f"(c0), "+f"(c1), "+f"(c2), "+f"(c3)
        : "r"(a0), "r"(a1), "r"(a2), "r"(a3), "r"(b0), "r"(b1));
}

// ---------------------------------------------------------------------------
// Fused prep kernel: blocks [0, NB_ROW) build row_start (transition scan),
// blocks [NB_ROW, NB_ROW+NB_GEMM) compute g = half(feat @ W^T) via tf32 mma.
// Independent work -> overlaps on chip instead of serializing two launches.
// ---------------------------------------------------------------------------
#define SM_PAD 68
__global__ __launch_bounds__(256) void prep_kernel(const int* __restrict__ edge_row,
                                                   int* __restrict__ row_start,
                                                   const float* __restrict__ feat,
                                                   const float* __restrict__ W,
                                                   __half* __restrict__ g) {
    __shared__ float sA[64 * SM_PAD];  // feat tile [r][k]
    __shared__ float sB[64 * SM_PAD];  // W [n][k]

    if (blockIdx.x < NB_ROW) {
        // ---- rowptr: 4 edges per thread, transitions only ----
        int t = blockIdx.x * blockDim.x + threadIdx.x;
        if (t >= N_EDGES / 4) return;
        int4 r4 = ((const int4*)edge_row)[t];
        int e0 = t * 4;
        int prev = (t == 0) ? -1 : __ldg(&edge_row[e0 - 1]);

        for (int q = prev + 1; q <= r4.x; ++q) row_start[q] = e0;
        for (int q = r4.x + 1; q <= r4.y; ++q) row_start[q] = e0 + 1;
        for (int q = r4.y + 1; q <= r4.z; ++q) row_start[q] = e0 + 2;
        for (int q = r4.z + 1; q <= r4.w; ++q) row_start[q] = e0 + 3;

        if (e0 + 4 == N_EDGES)
            for (int q = r4.w + 1; q <= N_NODES; ++q) row_start[q] = N_EDGES;
        return;
    }

    // ---- GEMM: tile 64 rows x 64 cols, 8 warps (4x2) ----
    int tid  = threadIdx.x;
    int lane = tid & 31;
    int warp = tid >> 5;
    int row0 = (blockIdx.x - NB_ROW) * 64;
    int maxrow = N_NODES - row0;

    for (int idx = tid; idx < 64 * 16; idx += 256) {
        int n = idx >> 4, q = idx & 15;
        float4 v = ((const float4*)W)[idx];
        float* dst = &sB[n * SM_PAD + q * 4];
        dst[0] = v.x; dst[1] = v.y; dst[2] = v.z; dst[3] = v.w;
    }
    for (int idx = tid; idx < 64 * 16; idx += 256) {
        int r = idx >> 4, q = idx & 15;
        float4 v = (r < maxrow) ? __ldcs(&((const float4*)(feat + (size_t)row0 * 64))[idx])
                                : make_float4(0.f, 0.f, 0.f, 0.f);
        float* dst = &sA[r * SM_PAD + q * 4];
        dst[0] = v.x; dst[1] = v.y; dst[2] = v.z; dst[3] = v.w;
    }
    __syncthreads();

    int g4 = lane >> 2;
    int t4 = lane & 3;
    int warp_m = warp >> 1;
    int warp_n = warp & 1;

    float acc[4][4];
    #pragma unroll
    for (int i = 0; i < 4; ++i)
        #pragma unroll
        for (int j = 0; j < 4; ++j) acc[i][j] = 0.f;

    int ra = warp_m * 16 + g4;

    #pragma unroll
    for (int ks = 0; ks < 8; ++ks) {
        int k0 = ks * 8;
        unsigned a0 = f2tf32(sA[ra * SM_PAD + k0 + t4]);
        unsigned a1 = f2tf32(sA[(ra + 8) * SM_PAD + k0 + t4]);
        unsigned a2 = f2tf32(sA[ra * SM_PAD + k0 + t4 + 4]);
        unsigned a3 = f2tf32(sA[(ra + 8) * SM_PAD + k0 + t4 + 4]);
        #pragma unroll
        for (int nt = 0; nt < 4; ++nt) {
            int n = (warp_n * 4 + nt) * 8 + g4;
            unsigned b0 = f2tf32(sB[n * SM_PAD + k0 + t4]);
            unsigned b1 = f2tf32(sB[n * SM_PAD + k0 + t4 + 4]);
            mma_tf32(acc[nt][0], acc[nt][1], acc[nt][2], acc[nt][3],
                     a0, a1, a2, a3, b0, b1);
        }
    }

    #pragma unroll
    for (int nt = 0; nt < 4; ++nt) {
        int col = (warp_n * 4 + nt) * 8 + 2 * t4;
        if (ra < maxrow) {
            __half2 h = __floats2half2_rn(acc[nt][0], acc[nt][1]);
            *(__half2*)(g + (size_t)(row0 + ra) * 64 + col) = h;
        }
        if (ra + 8 < maxrow) {
            __half2 h = __floats2half2_rn(acc[nt][2], acc[nt][3]);
            *(__half2*)(g + (size_t)(row0 + ra + 8) * 64 + col) = h;
        }
    }
}

// ---------------------------------------------------------------------------
// SpMM: one warp per node. 16 lanes per edge (2 edges per warp "slot"):
//   lane = half*16 + sub; lane loads uint2 (4 fp16 feats) of row c[edge].
// Edge (col,val) loaded cooperatively (32 at a time) and shfl-broadcast.
// Per edge: 0.5 gather LDG + ~0.06 scalar LDG -> LSU floor ~2 cyc/edge;
// binder becomes L2 gather bandwidth (~19us).
// ---------------------------------------------------------------------------
__global__ __launch_bounds__(256) void spmm_kernel(const int* __restrict__ row_start,
                                                   const int* __restrict__ edge_col,
                                                   const float* __restrict__ edge_val,
                                                   const __half* __restrict__ g,
                                                   const float* __restrict__ b,
                                                   float* __restrict__ out) {
    int warp_id = (blockIdx.x * blockDim.x + threadIdx.x) >> 5;
    int lane = threadIdx.x & 31;
    if (warp_id >= N_NODES) return;

    int half = lane >> 4;
    int sub  = lane & 15;

    int s = row_start[warp_id];
    int e = row_start[warp_id + 1];

    const uint2* gp = (const uint2*)g;   // row = 16 uint2 (128 B)
    float4 acc = make_float4(0.f, 0.f, 0.f, 0.f);

    for (int base = s; base < e; base += 32) {
        int cnt = min(32, e - base);
        int   c_l = 0;
        float v_l = 0.f;
        if (lane < cnt) {
            c_l = __ldcs(&edge_col[base + lane]);
            v_l = __ldcs(&edge_val[base + lane]);
        }

        int j = 0;
        // 8 edges (4 warp-slots) per unrolled iter -> MLP 4
        for (; j + 8 <= cnt; j += 8) {
            int m0 = j + half, m1 = j + 2 + half, m2 = j + 4 + half, m3 = j + 6 + half;
            int c0 = __shfl_sync(0xffffffffu, c_l, m0);
            int c1 = __shfl_sync(0xffffffffu, c_l, m1);
            int c2 = __shfl_sync(0xffffffffu, c_l, m2);
            int c3 = __shfl_sync(0xffffffffu, c_l, m3);
            float v0 = __shfl_sync(0xffffffffu, v_l, m0);
            float v1 = __shfl_sync(0xffffffffu, v_l, m1);
            float v2 = __shfl_sync(0xffffffffu, v_l, m2);
            float v3 = __shfl_sync(0xffffffffu, v_l, m3);
            uint2 a0 = gp[(size_t)c0 * 16 + sub];
            uint2 a1 = gp[(size_t)c1 * 16 + sub];
            uint2 a2 = gp[(size_t)c2 * 16 + sub];
            uint2 a3 = gp[(size_t)c3 * 16 + sub];
            {
                float2 lo = __half22float2(*(const __half2*)&a0.x);
                float2 hi = __half22float2(*(const __half2*)&a0.y);
                acc.x = fmaf(v0, lo.x, acc.x); acc.y = fmaf(v0, lo.y, acc.y);
                acc.z = fmaf(v0, hi.x, acc.z); acc.w = fmaf(v0, hi.y, acc.w);
            }
            {
                float2 lo = __half22float2(*(const __half2*)&a1.x);
                float2 hi = __half22float2(*(const __half2*)&a1.y);
                acc.x = fmaf(v1, lo.x, acc.x); acc.y = fmaf(v1, lo.y, acc.y);
                acc.z = fmaf(v1, hi.x, acc.z); acc.w = fmaf(v1, hi.y, acc.w);
            }
            {
                float2 lo = __half22float2(*(const __half2*)&a2.x);
                float2 hi = __half22float2(*(const __half2*)&a2.y);
                acc.x = fmaf(v2, lo.x, acc.x); acc.y = fmaf(v2, lo.y, acc.y);
                acc.z = fmaf(v2, hi.x, acc.z); acc.w = fmaf(v2, hi.y, acc.w);
            }
            {
                float2 lo = __half22float2(*(const __half2*)&a3.x);
                float2 hi = __half22float2(*(const __half2*)&a3.y);
                acc.x = fmaf(v3, lo.x, acc.x); acc.y = fmaf(v3, lo.y, acc.y);
                acc.z = fmaf(v3, hi.x, acc.z); acc.w = fmaf(v3, hi.y, acc.w);
            }
        }
        // tail: 2 edges per iter, upper half predicated on last odd edge
        for (; j < cnt; j += 2) {
            int m = j + half;
            int   c = __shfl_sync(0xffffffffu, c_l, m & 31);
            float v = __shfl_sync(0xffffffffu, v_l, m & 31);
            if (m < cnt) {
                uint2 a = gp[(size_t)c * 16 + sub];
                float2 lo = __half22float2(*(const __half2*)&a.x);
                float2 hi = __half22float2(*(const __half2*)&a.y);
                acc.x = fmaf(v, lo.x, acc.x); acc.y = fmaf(v, lo.y, acc.y);
                acc.z = fmaf(v, hi.x, acc.z); acc.w = fmaf(v, hi.y, acc.w);
            }
        }
    }

    // combine the two halves (features are partitioned identically by sub)
    acc.x += __shfl_xor_sync(0xffffffffu, acc.x, 16);
    acc.y += __shfl_xor_sync(0xffffffffu, acc.y, 16);
    acc.z += __shfl_xor_sync(0xffffffffu, acc.z, 16);
    acc.w += __shfl_xor_sync(0xffffffffu, acc.w, 16);

    if (half == 0) {
        float4 bv = ((const float4*)b)[sub];
        float4 r = make_float4(acc.x + bv.x, acc.y + bv.y, acc.z + bv.z, acc.w + bv.w);
        __stcs(&((float4*)(out + (size_t)warp_id * 64))[sub], r);
    }
}

// ---------------------------------------------------------------------------
extern "C" void kernel_launch(void* const* d_in, const int* in_sizes, int n_in,
                              void* d_out, int out_size) {
    const float* feat     = (const float*)d_in[0];
    const int*   edge_row = (const int*)  d_in[1];
    const int*   edge_col = (const int*)  d_in[2];
    const float* edge_val = (const float*)d_in[3];
    const float* W        = (const float*)d_in[4];
    const float* b        = (const float*)d_in[5];
    float*       out      = (float*)d_out;

    __half* g;
    int*    row_start;
    cudaGetSymbolAddress((void**)&g, g_buf);
    cudaGetSymbolAddress((void**)&row_start, g_row_start);

    // 1) fused: rowptr scan + g = half(feat @ W^T)   (independent, overlapped)
    prep_kernel<<<NB_ROW + NB_GEMM, 256>>>(edge_row, row_start, feat, W, g);

    // 2) out = A @ g + b   (one warp per node, 2 edges per warp-slot)
    int total_threads = N_NODES * 32;
    spmm_kernel<<<(total_threads + 255) / 256, 256>>>(row_start, edge_col, edge_val,
                                                      g, b, out);
}